// round 16
// baseline (speedup 1.0000x reference)
#include <cuda_runtime.h>
#include <cuda_fp16.h>
#include <cstdint>
#include <cstddef>

typedef unsigned int u32;
typedef unsigned long long u64;

#define BB 4
#define HH 256
#define WW 256
#define HWP (HH * WW)
#define NPIX (BB * HWP)
#define CPAD 228

// ---------------- device global scratch ----------------
__device__ __half g_p6h[(size_t)NPIX * 16], g_p6l[(size_t)NPIX * 16];
__device__ __half g_pAh[(size_t)NPIX * 64], g_pAl[(size_t)NPIX * 64];
__device__ __half g_pBh[(size_t)NPIX * 64], g_pBl[(size_t)NPIX * 64];
__device__ __half g_pCh[(size_t)NPIX * 64], g_pCl[(size_t)NPIX * 64];
// core, tap-major per 128px strip: [b][y][xblk(2)][tap(228)][px(128)]
__device__ float  g_core2[(size_t)NPIX * CPAD];
__device__ u32    g_wfrag[188928];

#define SWZ128(o) ((o) ^ (((o) >> 3) & 0x70))

__device__ __forceinline__ u32 smem_u32(const void* p) {
    u32 a;
    asm("{ .reg .u64 t; cvta.to.shared.u64 t, %1; cvt.u32.u64 %0, t; }" : "=r"(a) : "l"(p));
    return a;
}

#define LDSM4(r, a) asm volatile( \
    "ldmatrix.sync.aligned.m8n8.x4.shared.b16 {%0,%1,%2,%3}, [%4];" \
    : "=r"((r)[0]), "=r"((r)[1]), "=r"((r)[2]), "=r"((r)[3]) : "r"(a))

#define MMAF16(d, a, b0v, b1v) asm volatile( \
    "mma.sync.aligned.m16n8k16.row.col.f32.f16.f16.f32 " \
    "{%0,%1,%2,%3}, {%4,%5,%6,%7}, {%8,%9}, {%0,%1,%2,%3};" \
    : "+f"((d)[0]), "+f"((d)[1]), "+f"((d)[2]), "+f"((d)[3]) \
    : "r"((a)[0]), "r"((a)[1]), "r"((a)[2]), "r"((a)[3]), "r"(b0v), "r"(b1v))

// exp(|x|): magic-constant 2^n + degree-4 Taylor for 2^f (FMA/ALU only)
__device__ __forceinline__ float fexp_abs(float x)
{
    float t = fabsf(x) * 1.4426950408889634f;
    float k = t + 12582912.0f;
    float f = t - (k - 12582912.0f);
    float p = 9.6181291e-3f;
    p = fmaf(p, f, 5.5504109e-2f);
    p = fmaf(p, f, 2.4022651e-1f);
    p = fmaf(p, f, 6.9314718e-1f);
    p = fmaf(p, f, 1.0f);
    int e = (__float_as_int(k) - (0x4B400000 - 127)) << 23;
    return p * __int_as_float(e);
}

// ============================================================
// pack6: data_with_est [B,6,H,W] fp32 -> NHWC-16 fp16 hi/lo
// ============================================================
__global__ __launch_bounds__(256) void pack6_k(const float* __restrict__ in)
{
    int g = blockIdx.x * 256 + threadIdx.x;
    int b = g >> 16, p = g & 65535;
    alignas(16) __half h[16], l[16];
#pragma unroll
    for (int c = 0; c < 16; c++) { h[c] = __float2half(0.f); l[c] = __float2half(0.f); }
#pragma unroll
    for (int c = 0; c < 6; c++) {
        float v = in[((size_t)b * 6 + c) * HWP + p];
        __half hi = __float2half(v);
        h[c] = hi;
        l[c] = __float2half(v - __half2float(hi));
    }
    uint4* dh = reinterpret_cast<uint4*>(g_p6h + (size_t)g * 16);
    uint4* dl = reinterpret_cast<uint4*>(g_p6l + (size_t)g * 16);
    const uint4* sh = reinterpret_cast<const uint4*>(h);
    const uint4* sl = reinterpret_cast<const uint4*>(l);
#pragma unroll
    for (int i = 0; i < 2; i++) { dh[i] = sh[i]; dl[i] = sl[i]; }
}

// ============================================================
// wprep_all: weights -> per-lane mma B-fragments, LDG.128-paired.
// ============================================================
__global__ void wprep_all_k(const float* w0, const float* w1, const float* w2,
                            const float* w3, const float* w4, const float* w5,
                            const float* w6, const float* w7)
{
    const int segoff[8] = {0, 4608, 23040, 41472, 59904, 78336, 96768, 115200};
    const int segsz[8]  = {4608, 18432, 18432, 18432, 18432, 18432, 18432, 73728};
    const int seg = blockIdx.x >> 4;
    const int KS = (seg == 0) ? 1 : 4;
    const int TOTNP = (seg == 7) ? 16 : 4;
    const int OCs = (seg == 7) ? 225 : 64;
    const int ICs = (seg == 0) ? 6 : 64;
    const float* w;
    switch (seg) {
        case 0: w = w0; break; case 1: w = w1; break; case 2: w = w2; break;
        case 3: w = w3; break; case 4: w = w4; break; case 5: w = w5; break;
        case 6: w = w6; break; default: w = w7; break;
    }
    const int n = segsz[seg];
    const int dstoff = segoff[seg];
    for (int i = (blockIdx.x & 15) * 256 + threadIdx.x; i < n; i += 16 * 256) {
        int rem = i;
        int it  = rem / (TOTNP * 128); rem -= it * (TOTNP * 128);
        int np  = rem / 128;           rem -= np * 128;
        int lane = rem >> 2, r = rem & 3;
        int q = it % KS;
        int tap = it / KS;
        int nt = np * 2 + (r >> 1);
        int reg = r & 1;
        int nn = nt * 8 + (lane >> 2);
        int k0 = q * 16 + (lane & 3) * 2 + reg * 8;
        u32 outv = 0;
#pragma unroll
        for (int e = 0; e < 2; e++) {
            int k = k0 + e;
            float v = (nn < OCs && k < ICs) ? w[((size_t)nn * ICs + k) * 9 + tap] : 0.f;
            __half hb = __float2half(v);
            unsigned short bits = *reinterpret_cast<unsigned short*>(&hb);
            outv |= ((u32)bits) << (16 * e);
        }
        g_wfrag[dstoff + i] = outv;
    }
}

// ============================================================
// convS: 3x3 conv implicit GEMM.
// CTA: 256 thr (8 warps), tile = 64px x 4 rows x 64oc.
// warp = 32px of one (row, half). Smem: 6 y-planes, no A dup.
// B double-buffered. 2-pass fp16 hi/lo.
// OUTM epilogue writes tap-major core layout.
// ============================================================
template<int KS, int TOTNP, int CH, bool RELU, bool RESID, bool OUTM, int ROWB, int ICW>
__global__ __launch_bounds__(256, 2)
void convS_k(const __half* __restrict__ inh, const __half* __restrict__ inl,
             const __half* __restrict__ rh,  const __half* __restrict__ rl,
             __half* __restrict__ outh, __half* __restrict__ outl,
             float* __restrict__ outf, const float* __restrict__ bias,
             const u32* __restrict__ bfrag)
{
    extern __shared__ char smem[];
    const u32 sbase = smem_u32(smem);
    constexpr int PL = (ROWB == 128) ? 17408 : 6400;
    constexpr int LO = PL / 2;
    constexpr int IT = 9 * KS;

    const int tid  = threadIdx.x;
    const int lane = tid & 31;
    const int warp = tid >> 5;
    const int wrow = warp >> 1;
    const int wpx  = (warp & 1) * 32;

    const int x0 = blockIdx.x * 64;
    const int y0 = blockIdx.y * 4;
    const int b  = blockIdx.z;
    const size_t bbase = (size_t)b * HWP;

    // ---- stage 6 y-planes once ----
    constexpr int CCN = (ROWB == 128) ? 8 : 3;
    for (int i = tid; i < 6 * 66 * CCN; i += 256) {
        int pl  = i / (66 * CCN);
        int rem = i - pl * (66 * CCN);
        int row = rem / CCN, cc = rem % CCN;
        int gy = y0 + pl - 1, gx = x0 + row - 1;
        bool ok = (unsigned)gy < HH && (unsigned)gx < WW && (cc * 16 < ICW * 2);
        uint4 vh = make_uint4(0, 0, 0, 0), vl = vh;
        if (ok) {
            size_t gi = (bbase + (size_t)gy * WW + gx) * ICW + cc * 8;
            vh = *reinterpret_cast<const uint4*>(inh + gi);
            vl = *reinterpret_cast<const uint4*>(inl + gi);
        }
        u32 so = pl * PL + ((ROWB == 128) ? SWZ128((u32)(row * 128 + cc * 16))
                                          : (u32)(row * 48 + cc * 16));
        *reinterpret_cast<uint4*>(smem + so)      = vh;
        *reinterpret_cast<uint4*>(smem + so + LO) = vl;
    }
    __syncthreads();

    const int r16 = lane & 15, tk = lane >> 4;

    auto ldA = [&](int it, u32 (&Ad)[2][2][4]) {
        int tap = it / KS, q = it - tap * KS;
        int dy = tap / 3, dx = tap - dy * 3;
        u32 base = sbase + (wrow + dy) * PL;
#pragma unroll
        for (int mt = 0; mt < 2; mt++) {
            int row = wpx + mt * 16 + r16 + dx;
            u32 off = (ROWB == 128) ? SWZ128((u32)(row * 128 + q * 32 + tk * 16))
                                    : (u32)(row * 48 + tk * 16);
            LDSM4(Ad[mt][0], base + off);
            LDSM4(Ad[mt][1], base + LO + off);
        }
    };
    auto ldB = [&](int it, int chunk, uint4 (&Bd)[4]) {
        const u32* bp = bfrag + ((size_t)(it * TOTNP + chunk * 4)) * 128 + lane * 4;
#pragma unroll
        for (int np = 0; np < 4; np++)
            Bd[np] = *reinterpret_cast<const uint4*>(bp + np * 128);
    };

#pragma unroll 1
    for (int chunk = 0; chunk < CH; chunk++) {
        float acc[2][8][4];
#pragma unroll
        for (int mt = 0; mt < 2; mt++)
#pragma unroll
            for (int nt = 0; nt < 8; nt++)
#pragma unroll
                for (int e = 0; e < 4; e++) acc[mt][nt][e] = 0.f;

        auto domma = [&](u32 (&Ad)[2][2][4], uint4 (&Bd)[4]) {
#pragma unroll
            for (int np = 0; np < 4; np++) {
                u32 b0 = Bd[np].x, b1 = Bd[np].y;
                u32 b2 = Bd[np].z, b3 = Bd[np].w;
#pragma unroll
                for (int mt = 0; mt < 2; mt++) {
                    MMAF16(acc[mt][2 * np],     Ad[mt][0], b0, b1);
                    MMAF16(acc[mt][2 * np],     Ad[mt][1], b0, b1);
                    MMAF16(acc[mt][2 * np + 1], Ad[mt][0], b2, b3);
                    MMAF16(acc[mt][2 * np + 1], Ad[mt][1], b2, b3);
                }
            }
        };

        uint4 Bd0[4], Bd1[4];
        ldB(0, chunk, Bd0);
#pragma unroll 1
        for (int itp = 0; itp < IT / 2; itp++) {
            const int it0 = 2 * itp;
            ldB(it0 + 1, chunk, Bd1);
            {
                u32 Ad[2][2][4];
                ldA(it0, Ad);
                domma(Ad, Bd0);
            }
            if (it0 + 2 < IT) ldB(it0 + 2, chunk, Bd0);
            {
                u32 Ad[2][2][4];
                ldA(it0 + 1, Ad);
                domma(Ad, Bd1);
            }
        }
        if (IT & 1) {
            u32 Ad[2][2][4];
            ldA(IT - 1, Ad);
            domma(Ad, Bd0);
        }

        // ---- epilogue ----
        const int gy = y0 + wrow;
#pragma unroll
        for (int nt = 0; nt < 8; nt++) {
            int oc = (OUTM ? chunk * 64 : 0) + nt * 8 + (lane & 3) * 2;
            float bz0, bz1;
            if (OUTM) {
                bz0 = (oc < 225) ? bias[oc] : 0.f;
                bz1 = (oc + 1 < 225) ? bias[oc + 1] : 0.f;
            } else {
                bz0 = bias[oc]; bz1 = bias[oc + 1];
            }
#pragma unroll
            for (int mt = 0; mt < 2; mt++) {
#pragma unroll
                for (int rr = 0; rr < 2; rr++) {
                    int m = wpx + mt * 16 + (lane >> 2) + rr * 8;
                    float v0 = acc[mt][nt][rr * 2 + 0] + bz0;
                    float v1 = acc[mt][nt][rr * 2 + 1] + bz1;
                    if (OUTM) {
                        // tap-major core: [b][gy][xblk][tap][px]
                        int mloc = (blockIdx.x & 1) * 64 + m;
                        size_t cb = ((size_t)(b * HH + gy) * 2 + (blockIdx.x >> 1)) * (CPAD * 128);
                        if (oc < CPAD)     outf[cb + (size_t)oc * 128 + mloc]       = v0;
                        if (oc + 1 < CPAD) outf[cb + (size_t)(oc + 1) * 128 + mloc] = v1;
                    } else {
                        size_t pb = bbase + (size_t)gy * WW + x0 + m;
                        size_t ei = pb * 64 + oc;
                        if (RESID) {
                            u32 hh = *reinterpret_cast<const u32*>(rh + ei);
                            u32 ll = *reinterpret_cast<const u32*>(rl + ei);
                            __half2 h2 = *reinterpret_cast<__half2*>(&hh);
                            __half2 l2 = *reinterpret_cast<__half2*>(&ll);
                            v0 += __half2float(h2.x) + __half2float(l2.x);
                            v1 += __half2float(h2.y) + __half2float(l2.y);
                        }
                        if (RELU) { v0 = fmaxf(v0, 0.f); v1 = fmaxf(v1, 0.f); }
                        __half h0 = __float2half(v0);
                        __half h1 = __float2half(v1);
                        __half l0 = __float2half(v0 - __half2float(h0));
                        __half l1 = __float2half(v1 - __half2float(h1));
                        __half2 hv; hv.x = h0; hv.y = h1;
                        __half2 lv; lv.x = l0; lv.y = l1;
                        *reinterpret_cast<__half2*>(outh + ei) = hv;
                        *reinterpret_cast<__half2*>(outl + ei) = lv;
                    }
                }
            }
        }
    }
}

// ============================================================
// kpn: per-pixel softmax(|core|) over 225 taps + 15x15 filter.
// core tap-major -> fully coalesced reads, batched 15/row (MLP=15).
// ============================================================
__global__ __launch_bounds__(128)
void kpn2_k(const float* __restrict__ data, float* __restrict__ pred)
{
    __shared__ float4 sd[15 * 144];
    const int tid = threadIdx.x;
    const int x0 = blockIdx.x * 128;
    const int y  = blockIdx.y;
    const int b  = blockIdx.z;

    for (int i = tid; i < 15 * 142; i += 128) {
        int r = i / 142, q = i - r * 142;
        int gy = y - 7 + r, gx = x0 - 7 + q;
        float4 v = make_float4(0.f, 0.f, 0.f, 0.f);
        if ((unsigned)gy < HH && (unsigned)gx < WW) {
            size_t gi = (size_t)(b * 3) * HWP + (size_t)gy * WW + gx;
            v.x = data[gi];
            v.y = data[gi + HWP];
            v.z = data[gi + 2 * HWP];
        }
        sd[r * 144 + q] = v;
    }
    __syncthreads();

    const int px = tid;
    const float* cr = g_core2
        + ((size_t)(b * HH + y) * 2 + blockIdx.x) * (CPAD * 128) + px;

    float S = 0.f, P0 = 0.f, P1 = 0.f, P2 = 0.f;
#pragma unroll 1
    for (int ki = 0; ki < 15; ki++) {
        float cv[15];
#pragma unroll
        for (int kj = 0; kj < 15; kj++)
            cv[kj] = cr[(size_t)(ki * 15 + kj) * 128];
#pragma unroll
        for (int kj = 0; kj < 15; kj++) {
            float w = fexp_abs(cv[kj]);
            float4 d = sd[ki * 144 + px + kj];
            S  += w;
            P0 += w * d.x;
            P1 += w * d.y;
            P2 += w * d.z;
        }
    }
    float inv = 1.0f / S;
    size_t o = (size_t)b * 3 * HWP + (size_t)y * WW + x0 + px;
    pred[o]           = P0 * inv;
    pred[o + HWP]     = P1 * inv;
    pred[o + 2 * HWP] = P2 * inv;
}

// ============================================================
// launch
// ============================================================
template<typename T>
static T* sym(const void* s) { void* p = nullptr; cudaGetSymbolAddress(&p, s); return (T*)p; }

extern "C" void kernel_launch(void* const* d_in, const int* in_sizes, int n_in,
                              void* d_out, int out_size)
{
    const float* dwe     = (const float*)d_in[0];
    const float* data    = (const float*)d_in[1];
    const float* w_first = (const float*)d_in[2];
    const float* b_first = (const float*)d_in[3];
    const float* w1a = (const float*)d_in[4];  const float* b1a = (const float*)d_in[5];
    const float* w1b = (const float*)d_in[6];  const float* b1b = (const float*)d_in[7];
    const float* w2a = (const float*)d_in[8];  const float* b2a = (const float*)d_in[9];
    const float* w2b = (const float*)d_in[10]; const float* b2b = (const float*)d_in[11];
    const float* w3a = (const float*)d_in[12]; const float* b3a = (const float*)d_in[13];
    const float* w3b = (const float*)d_in[14]; const float* b3b = (const float*)d_in[15];
    const float* w_out = (const float*)d_in[16]; const float* b_out = (const float*)d_in[17];

    __half* p6h = sym<__half>(g_p6h); __half* p6l = sym<__half>(g_p6l);
    __half* pAh = sym<__half>(g_pAh); __half* pAl = sym<__half>(g_pAl);
    __half* pBh = sym<__half>(g_pBh); __half* pBl = sym<__half>(g_pBl);
    __half* pCh = sym<__half>(g_pCh); __half* pCl = sym<__half>(g_pCl);
    float* core2 = sym<float>(g_core2);
    const u32* wf = sym<u32>(g_wfrag);

    constexpr int SM128 = 6 * 17408;   // 104448
    constexpr int SM48  = 6 * 6400;    // 38400

    static bool once = false;
    if (!once) {
        cudaFuncSetAttribute(convS_k<1, 4, 1, false, false, false, 48, 16>,
                             cudaFuncAttributeMaxDynamicSharedMemorySize, SM48);
        cudaFuncSetAttribute(convS_k<4, 4, 1, true,  false, false, 128, 64>,
                             cudaFuncAttributeMaxDynamicSharedMemorySize, SM128);
        cudaFuncSetAttribute(convS_k<4, 4, 1, false, true,  false, 128, 64>,
                             cudaFuncAttributeMaxDynamicSharedMemorySize, SM128);
        cudaFuncSetAttribute(convS_k<4, 16, 4, false, false, true, 128, 64>,
                             cudaFuncAttributeMaxDynamicSharedMemorySize, SM128);
        once = true;
    }

    pack6_k<<<NPIX / 256, 256>>>(dwe);
    wprep_all_k<<<128, 256>>>(w_first, w1a, w1b, w2a, w2b, w3a, w3b, w_out);

    cudaMemcpyAsync(d_out, data, (size_t)BB * 3 * HWP * sizeof(float),
                    cudaMemcpyDeviceToDevice, 0);

    dim3 gridC(4, 64, 4), blk(256);
    convS_k<1, 4, 1, false, false, false, 48, 16><<<gridC, blk, SM48>>>(
        p6h, p6l, nullptr, nullptr, pAh, pAl, nullptr, b_first, wf + 0);
    convS_k<4, 4, 1, true,  false, false, 128, 64><<<gridC, blk, SM128>>>(
        pAh, pAl, nullptr, nullptr, pBh, pBl, nullptr, b1a, wf + 4608);
    convS_k<4, 4, 1, false, true,  false, 128, 64><<<gridC, blk, SM128>>>(
        pBh, pBl, pAh, pAl, pCh, pCl, nullptr, b1b, wf + 23040);
    convS_k<4, 4, 1, true,  false, false, 128, 64><<<gridC, blk, SM128>>>(
        pCh, pCl, nullptr, nullptr, pBh, pBl, nullptr, b2a, wf + 41472);
    convS_k<4, 4, 1, false, true,  false, 128, 64><<<gridC, blk, SM128>>>(
        pBh, pBl, pCh, pCl, pAh, pAl, nullptr, b2b, wf + 59904);
    convS_k<4, 4, 1, true,  false, false, 128, 64><<<gridC, blk, SM128>>>(
        pAh, pAl, nullptr, nullptr, pBh, pBl, nullptr, b3a, wf + 78336);
    convS_k<4, 4, 1, false, true,  false, 128, 64><<<gridC, blk, SM128>>>(
        pBh, pBl, pAh, pAl, pCh, pCl, nullptr, b3b, wf + 96768);

    convS_k<4, 16, 4, false, false, true, 128, 64><<<gridC, blk, SM128>>>(
        pCh, pCl, nullptr, nullptr, nullptr, nullptr, core2, b_out, wf + 115200);

    kpn2_k<<<dim3(2, 256, 4), 128>>>(data, (float*)d_out + (size_t)BB * 3 * HWP);
}

// round 17
// speedup vs baseline: 1.1875x; 1.1875x over previous
#include <cuda_runtime.h>
#include <cuda_fp16.h>
#include <cstdint>
#include <cstddef>

typedef unsigned int u32;
typedef unsigned long long u64;

#define BB 4
#define HH 256
#define WW 256
#define HWP (HH * WW)
#define NPIX (BB * HWP)
#define CPAD 228

// ---------------- device global scratch ----------------
__device__ __half g_p6h[(size_t)NPIX * 16], g_p6l[(size_t)NPIX * 16];
__device__ __half g_pAh[(size_t)NPIX * 64], g_pAl[(size_t)NPIX * 64];
__device__ __half g_pBh[(size_t)NPIX * 64], g_pBl[(size_t)NPIX * 64];
__device__ __half g_pCh[(size_t)NPIX * 64], g_pCl[(size_t)NPIX * 64];
__device__ float  g_core2[(size_t)NPIX * CPAD];   // px-major: [px][tap]
__device__ u32    g_wfrag[188928];

#define SWZ128(o) ((o) ^ (((o) >> 3) & 0x70))

__device__ __forceinline__ u32 smem_u32(const void* p) {
    u32 a;
    asm("{ .reg .u64 t; cvta.to.shared.u64 t, %1; cvt.u32.u64 %0, t; }" : "=r"(a) : "l"(p));
    return a;
}

#define LDSM4(r, a) asm volatile( \
    "ldmatrix.sync.aligned.m8n8.x4.shared.b16 {%0,%1,%2,%3}, [%4];" \
    : "=r"((r)[0]), "=r"((r)[1]), "=r"((r)[2]), "=r"((r)[3]) : "r"(a))

#define MMAF16(d, a, b0v, b1v) asm volatile( \
    "mma.sync.aligned.m16n8k16.row.col.f32.f16.f16.f32 " \
    "{%0,%1,%2,%3}, {%4,%5,%6,%7}, {%8,%9}, {%0,%1,%2,%3};" \
    : "+f"((d)[0]), "+f"((d)[1]), "+f"((d)[2]), "+f"((d)[3]) \
    : "r"((a)[0]), "r"((a)[1]), "r"((a)[2]), "r"((a)[3]), "r"(b0v), "r"(b1v))

// exp(|x|): magic-constant 2^n + degree-4 Taylor for 2^f (FMA/ALU only)
__device__ __forceinline__ float fexp_abs(float x)
{
    float t = fabsf(x) * 1.4426950408889634f;
    float k = t + 12582912.0f;
    float f = t - (k - 12582912.0f);
    float p = 9.6181291e-3f;
    p = fmaf(p, f, 5.5504109e-2f);
    p = fmaf(p, f, 2.4022651e-1f);
    p = fmaf(p, f, 6.9314718e-1f);
    p = fmaf(p, f, 1.0f);
    int e = (__float_as_int(k) - (0x4B400000 - 127)) << 23;
    return p * __int_as_float(e);
}

// ============================================================
// pack6: data_with_est [B,6,H,W] fp32 -> NHWC-16 fp16 hi/lo
// ============================================================
__global__ __launch_bounds__(256) void pack6_k(const float* __restrict__ in)
{
    int g = blockIdx.x * 256 + threadIdx.x;
    int b = g >> 16, p = g & 65535;
    alignas(16) __half h[16], l[16];
#pragma unroll
    for (int c = 0; c < 16; c++) { h[c] = __float2half(0.f); l[c] = __float2half(0.f); }
#pragma unroll
    for (int c = 0; c < 6; c++) {
        float v = in[((size_t)b * 6 + c) * HWP + p];
        __half hi = __float2half(v);
        h[c] = hi;
        l[c] = __float2half(v - __half2float(hi));
    }
    uint4* dh = reinterpret_cast<uint4*>(g_p6h + (size_t)g * 16);
    uint4* dl = reinterpret_cast<uint4*>(g_p6l + (size_t)g * 16);
    const uint4* sh = reinterpret_cast<const uint4*>(h);
    const uint4* sl = reinterpret_cast<const uint4*>(l);
#pragma unroll
    for (int i = 0; i < 2; i++) { dh[i] = sh[i]; dl[i] = sl[i]; }
}

// ============================================================
// wprep_all: weights -> per-lane mma B-fragments, LDG.128-paired.
// ============================================================
__global__ void wprep_all_k(const float* w0, const float* w1, const float* w2,
                            const float* w3, const float* w4, const float* w5,
                            const float* w6, const float* w7)
{
    const int segoff[8] = {0, 4608, 23040, 41472, 59904, 78336, 96768, 115200};
    const int segsz[8]  = {4608, 18432, 18432, 18432, 18432, 18432, 18432, 73728};
    const int seg = blockIdx.x >> 4;
    const int KS = (seg == 0) ? 1 : 4;
    const int TOTNP = (seg == 7) ? 16 : 4;
    const int OCs = (seg == 7) ? 225 : 64;
    const int ICs = (seg == 0) ? 6 : 64;
    const float* w;
    switch (seg) {
        case 0: w = w0; break; case 1: w = w1; break; case 2: w = w2; break;
        case 3: w = w3; break; case 4: w = w4; break; case 5: w = w5; break;
        case 6: w = w6; break; default: w = w7; break;
    }
    const int n = segsz[seg];
    const int dstoff = segoff[seg];
    for (int i = (blockIdx.x & 15) * 256 + threadIdx.x; i < n; i += 16 * 256) {
        int rem = i;
        int it  = rem / (TOTNP * 128); rem -= it * (TOTNP * 128);
        int np  = rem / 128;           rem -= np * 128;
        int lane = rem >> 2, r = rem & 3;
        int q = it % KS;
        int tap = it / KS;
        int nt = np * 2 + (r >> 1);
        int reg = r & 1;
        int nn = nt * 8 + (lane >> 2);
        int k0 = q * 16 + (lane & 3) * 2 + reg * 8;
        u32 outv = 0;
#pragma unroll
        for (int e = 0; e < 2; e++) {
            int k = k0 + e;
            float v = (nn < OCs && k < ICs) ? w[((size_t)nn * ICs + k) * 9 + tap] : 0.f;
            __half hb = __float2half(v);
            unsigned short bits = *reinterpret_cast<unsigned short*>(&hb);
            outv |= ((u32)bits) << (16 * e);
        }
        g_wfrag[dstoff + i] = outv;
    }
}

// ============================================================
// convS: 3x3 conv implicit GEMM (identical to R15 best).
// CTA: 256 thr (8 warps), tile = 64px x 4 rows x 64oc.
// warp = 32px of one (row, half). Smem: 6 y-planes, no A dup.
// B double-buffered. 2-pass fp16 hi/lo.
// ============================================================
template<int KS, int TOTNP, int CH, bool RELU, bool RESID, bool OUTM, int ROWB, int ICW>
__global__ __launch_bounds__(256, 2)
void convS_k(const __half* __restrict__ inh, const __half* __restrict__ inl,
             const __half* __restrict__ rh,  const __half* __restrict__ rl,
             __half* __restrict__ outh, __half* __restrict__ outl,
             float* __restrict__ outf, const float* __restrict__ bias,
             const u32* __restrict__ bfrag)
{
    extern __shared__ char smem[];
    const u32 sbase = smem_u32(smem);
    constexpr int PL = (ROWB == 128) ? 17408 : 6400;
    constexpr int LO = PL / 2;
    constexpr int IT = 9 * KS;

    const int tid  = threadIdx.x;
    const int lane = tid & 31;
    const int warp = tid >> 5;
    const int wrow = warp >> 1;
    const int wpx  = (warp & 1) * 32;

    const int x0 = blockIdx.x * 64;
    const int y0 = blockIdx.y * 4;
    const int b  = blockIdx.z;
    const size_t bbase = (size_t)b * HWP;

    // ---- stage 6 y-planes once ----
    constexpr int CCN = (ROWB == 128) ? 8 : 3;
    for (int i = tid; i < 6 * 66 * CCN; i += 256) {
        int pl  = i / (66 * CCN);
        int rem = i - pl * (66 * CCN);
        int row = rem / CCN, cc = rem % CCN;
        int gy = y0 + pl - 1, gx = x0 + row - 1;
        bool ok = (unsigned)gy < HH && (unsigned)gx < WW && (cc * 16 < ICW * 2);
        uint4 vh = make_uint4(0, 0, 0, 0), vl = vh;
        if (ok) {
            size_t gi = (bbase + (size_t)gy * WW + gx) * ICW + cc * 8;
            vh = *reinterpret_cast<const uint4*>(inh + gi);
            vl = *reinterpret_cast<const uint4*>(inl + gi);
        }
        u32 so = pl * PL + ((ROWB == 128) ? SWZ128((u32)(row * 128 + cc * 16))
                                          : (u32)(row * 48 + cc * 16));
        *reinterpret_cast<uint4*>(smem + so)      = vh;
        *reinterpret_cast<uint4*>(smem + so + LO) = vl;
    }
    __syncthreads();

    const int r16 = lane & 15, tk = lane >> 4;

    auto ldA = [&](int it, u32 (&Ad)[2][2][4]) {
        int tap = it / KS, q = it - tap * KS;
        int dy = tap / 3, dx = tap - dy * 3;
        u32 base = sbase + (wrow + dy) * PL;
#pragma unroll
        for (int mt = 0; mt < 2; mt++) {
            int row = wpx + mt * 16 + r16 + dx;
            u32 off = (ROWB == 128) ? SWZ128((u32)(row * 128 + q * 32 + tk * 16))
                                    : (u32)(row * 48 + tk * 16);
            LDSM4(Ad[mt][0], base + off);
            LDSM4(Ad[mt][1], base + LO + off);
        }
    };
    auto ldB = [&](int it, int chunk, uint4 (&Bd)[4]) {
        const u32* bp = bfrag + ((size_t)(it * TOTNP + chunk * 4)) * 128 + lane * 4;
#pragma unroll
        for (int np = 0; np < 4; np++)
            Bd[np] = *reinterpret_cast<const uint4*>(bp + np * 128);
    };

#pragma unroll 1
    for (int chunk = 0; chunk < CH; chunk++) {
        float acc[2][8][4];
#pragma unroll
        for (int mt = 0; mt < 2; mt++)
#pragma unroll
            for (int nt = 0; nt < 8; nt++)
#pragma unroll
                for (int e = 0; e < 4; e++) acc[mt][nt][e] = 0.f;

        auto domma = [&](u32 (&Ad)[2][2][4], uint4 (&Bd)[4]) {
#pragma unroll
            for (int np = 0; np < 4; np++) {
                u32 b0 = Bd[np].x, b1 = Bd[np].y;
                u32 b2 = Bd[np].z, b3 = Bd[np].w;
#pragma unroll
                for (int mt = 0; mt < 2; mt++) {
                    MMAF16(acc[mt][2 * np],     Ad[mt][0], b0, b1);
                    MMAF16(acc[mt][2 * np],     Ad[mt][1], b0, b1);
                    MMAF16(acc[mt][2 * np + 1], Ad[mt][0], b2, b3);
                    MMAF16(acc[mt][2 * np + 1], Ad[mt][1], b2, b3);
                }
            }
        };

        uint4 Bd0[4], Bd1[4];
        ldB(0, chunk, Bd0);
#pragma unroll 1
        for (int itp = 0; itp < IT / 2; itp++) {
            const int it0 = 2 * itp;
            ldB(it0 + 1, chunk, Bd1);
            {
                u32 Ad[2][2][4];
                ldA(it0, Ad);
                domma(Ad, Bd0);
            }
            if (it0 + 2 < IT) ldB(it0 + 2, chunk, Bd0);
            {
                u32 Ad[2][2][4];
                ldA(it0 + 1, Ad);
                domma(Ad, Bd1);
            }
        }
        if (IT & 1) {
            u32 Ad[2][2][4];
            ldA(IT - 1, Ad);
            domma(Ad, Bd0);
        }

        // ---- epilogue (px-major core; identical to R15) ----
        const int gy = y0 + wrow;
#pragma unroll
        for (int nt = 0; nt < 8; nt++) {
            int oc = (OUTM ? chunk * 64 : 0) + nt * 8 + (lane & 3) * 2;
            float bz0, bz1;
            if (OUTM) {
                bz0 = (oc < 225) ? bias[oc] : 0.f;
                bz1 = (oc + 1 < 225) ? bias[oc + 1] : 0.f;
            } else {
                bz0 = bias[oc]; bz1 = bias[oc + 1];
            }
#pragma unroll
            for (int mt = 0; mt < 2; mt++) {
#pragma unroll
                for (int rr = 0; rr < 2; rr++) {
                    int m = wpx + mt * 16 + (lane >> 2) + rr * 8;
                    size_t pb = bbase + (size_t)gy * WW + x0 + m;
                    float v0 = acc[mt][nt][rr * 2 + 0] + bz0;
                    float v1 = acc[mt][nt][rr * 2 + 1] + bz1;
                    if (OUTM) {
                        if (oc < 228)
                            *reinterpret_cast<float2*>(outf + pb * CPAD + oc) = make_float2(v0, v1);
                    } else {
                        size_t ei = pb * 64 + oc;
                        if (RESID) {
                            u32 hh = *reinterpret_cast<const u32*>(rh + ei);
                            u32 ll = *reinterpret_cast<const u32*>(rl + ei);
                            __half2 h2 = *reinterpret_cast<__half2*>(&hh);
                            __half2 l2 = *reinterpret_cast<__half2*>(&ll);
                            v0 += __half2float(h2.x) + __half2float(l2.x);
                            v1 += __half2float(h2.y) + __half2float(l2.y);
                        }
                        if (RELU) { v0 = fmaxf(v0, 0.f); v1 = fmaxf(v1, 0.f); }
                        __half h0 = __float2half(v0);
                        __half h1 = __float2half(v1);
                        __half l0 = __float2half(v0 - __half2float(h0));
                        __half l1 = __float2half(v1 - __half2float(h1));
                        __half2 hv; hv.x = h0; hv.y = h1;
                        __half2 lv; lv.x = l0; lv.y = l1;
                        *reinterpret_cast<__half2*>(outh + ei) = hv;
                        *reinterpret_cast<__half2*>(outl + ei) = lv;
                    }
                }
            }
        }
    }
}

// ============================================================
// kpn: softmax(|core|) over 225 taps + 15x15 filter.
// px-major core, but reads staged through smem in 4 chunks of
// 57 taps x 128 px: gmem loads are cooperative & sector-coalesced,
// compute reads smem with odd stride 59 (conflict-free).
// ============================================================
#define KPN_SMEM (15 * 144 * 16 + 128 * 59 * 4)   // sd + sc = 34560 + 30208

__global__ __launch_bounds__(128)
void kpn3_k(const float* __restrict__ data, float* __restrict__ pred)
{
    extern __shared__ char dyn[];
    float4* sd = reinterpret_cast<float4*>(dyn);            // [15][144]
    float*  sc = reinterpret_cast<float*>(dyn + 15 * 144 * 16);  // [128][59]

    const int tid = threadIdx.x;
    const int x0 = blockIdx.x * 128;
    const int y  = blockIdx.y;
    const int b  = blockIdx.z;

    for (int i = tid; i < 15 * 142; i += 128) {
        int r = i / 142, q = i - r * 142;
        int gy = y - 7 + r, gx = x0 - 7 + q;
        float4 v = make_float4(0.f, 0.f, 0.f, 0.f);
        if ((unsigned)gy < HH && (unsigned)gx < WW) {
            size_t gi = (size_t)(b * 3) * HWP + (size_t)gy * WW + gx;
            v.x = data[gi];
            v.y = data[gi + HWP];
            v.z = data[gi + 2 * HWP];
        }
        sd[r * 144 + q] = v;
    }

    const size_t pbase = (size_t)b * HWP + (size_t)y * WW + x0;
    const float* cb = g_core2 + pbase * CPAD;

    float S = 0.f, P0 = 0.f, P1 = 0.f, P2 = 0.f;

#pragma unroll 1
    for (int c = 0; c < 4; c++) {
        __syncthreads();   // protect sc reuse (and sd readiness on c==0)
        // stage chunk: taps [c*57, c*57+57) for all 128 px, coalesced-ish
        const int t0 = c * 57;
        for (int i = tid; i < 128 * 57; i += 128) {
            int px = i / 57, col = i - px * 57;
            sc[px * 59 + col] = cb[(size_t)px * CPAD + t0 + col];
        }
        __syncthreads();

        int t = t0;
        int ki = t / 15, kj = t - ki * 15;
        const float* row = sc + tid * 59;
        const int jmax = (c == 3) ? 54 : 57;    // taps 225..227 excluded
#pragma unroll 19
        for (int j = 0; j < jmax; j++) {
            float w = fexp_abs(row[j]);
            float4 d = sd[ki * 144 + tid + kj];
            S  += w;
            P0 += w * d.x;
            P1 += w * d.y;
            P2 += w * d.z;
            if (++kj == 15) { kj = 0; ki++; }
        }
    }

    float inv = 1.0f / S;
    size_t o = (size_t)b * 3 * HWP + (size_t)y * WW + x0 + tid;
    pred[o]           = P0 * inv;
    pred[o + HWP]     = P1 * inv;
    pred[o + 2 * HWP] = P2 * inv;
}

// ============================================================
// launch
// ============================================================
template<typename T>
static T* sym(const void* s) { void* p = nullptr; cudaGetSymbolAddress(&p, s); return (T*)p; }

extern "C" void kernel_launch(void* const* d_in, const int* in_sizes, int n_in,
                              void* d_out, int out_size)
{
    const float* dwe     = (const float*)d_in[0];
    const float* data    = (const float*)d_in[1];
    const float* w_first = (const float*)d_in[2];
    const float* b_first = (const float*)d_in[3];
    const float* w1a = (const float*)d_in[4];  const float* b1a = (const float*)d_in[5];
    const float* w1b = (const float*)d_in[6];  const float* b1b = (const float*)d_in[7];
    const float* w2a = (const float*)d_in[8];  const float* b2a = (const float*)d_in[9];
    const float* w2b = (const float*)d_in[10]; const float* b2b = (const float*)d_in[11];
    const float* w3a = (const float*)d_in[12]; const float* b3a = (const float*)d_in[13];
    const float* w3b = (const float*)d_in[14]; const float* b3b = (const float*)d_in[15];
    const float* w_out = (const float*)d_in[16]; const float* b_out = (const float*)d_in[17];

    __half* p6h = sym<__half>(g_p6h); __half* p6l = sym<__half>(g_p6l);
    __half* pAh = sym<__half>(g_pAh); __half* pAl = sym<__half>(g_pAl);
    __half* pBh = sym<__half>(g_pBh); __half* pBl = sym<__half>(g_pBl);
    __half* pCh = sym<__half>(g_pCh); __half* pCl = sym<__half>(g_pCl);
    float* core2 = sym<float>(g_core2);
    const u32* wf = sym<u32>(g_wfrag);

    constexpr int SM128 = 6 * 17408;   // 104448
    constexpr int SM48  = 6 * 6400;    // 38400

    static bool once = false;
    if (!once) {
        cudaFuncSetAttribute(convS_k<1, 4, 1, false, false, false, 48, 16>,
                             cudaFuncAttributeMaxDynamicSharedMemorySize, SM48);
        cudaFuncSetAttribute(convS_k<4, 4, 1, true,  false, false, 128, 64>,
                             cudaFuncAttributeMaxDynamicSharedMemorySize, SM128);
        cudaFuncSetAttribute(convS_k<4, 4, 1, false, true,  false, 128, 64>,
                             cudaFuncAttributeMaxDynamicSharedMemorySize, SM128);
        cudaFuncSetAttribute(convS_k<4, 16, 4, false, false, true, 128, 64>,
                             cudaFuncAttributeMaxDynamicSharedMemorySize, SM128);
        cudaFuncSetAttribute(kpn3_k,
                             cudaFuncAttributeMaxDynamicSharedMemorySize, KPN_SMEM);
        once = true;
    }

    pack6_k<<<NPIX / 256, 256>>>(dwe);
    wprep_all_k<<<128, 256>>>(w_first, w1a, w1b, w2a, w2b, w3a, w3b, w_out);

    cudaMemcpyAsync(d_out, data, (size_t)BB * 3 * HWP * sizeof(float),
                    cudaMemcpyDeviceToDevice, 0);

    dim3 gridC(4, 64, 4), blk(256);
    convS_k<1, 4, 1, false, false, false, 48, 16><<<gridC, blk, SM48>>>(
        p6h, p6l, nullptr, nullptr, pAh, pAl, nullptr, b_first, wf + 0);
    convS_k<4, 4, 1, true,  false, false, 128, 64><<<gridC, blk, SM128>>>(
        pAh, pAl, nullptr, nullptr, pBh, pBl, nullptr, b1a, wf + 4608);
    convS_k<4, 4, 1, false, true,  false, 128, 64><<<gridC, blk, SM128>>>(
        pBh, pBl, pAh, pAl, pCh, pCl, nullptr, b1b, wf + 23040);
    convS_k<4, 4, 1, true,  false, false, 128, 64><<<gridC, blk, SM128>>>(
        pCh, pCl, nullptr, nullptr, pBh, pBl, nullptr, b2a, wf + 41472);
    convS_k<4, 4, 1, false, true,  false, 128, 64><<<gridC, blk, SM128>>>(
        pBh, pBl, pCh, pCl, pAh, pAl, nullptr, b2b, wf + 59904);
    convS_k<4, 4, 1, true,  false, false, 128, 64><<<gridC, blk, SM128>>>(
        pAh, pAl, nullptr, nullptr, pBh, pBl, nullptr, b3a, wf + 78336);
    convS_k<4, 4, 1, false, true,  false, 128, 64><<<gridC, blk, SM128>>>(
        pBh, pBl, pAh, pAl, pCh, pCl, nullptr, b3b, wf + 96768);

    convS_k<4, 16, 4, false, false, true, 128, 64><<<gridC, blk, SM128>>>(
        pCh, pCl, nullptr, nullptr, nullptr, nullptr, core2, b_out, wf + 115200);

    kpn3_k<<<dim3(2, 256, 4), 128, KPN_SMEM>>>(data, (float*)d_out + (size_t)BB * 3 * HWP);
}